// round 16
// baseline (speedup 1.0000x reference)
#include <cuda_runtime.h>
#include <math.h>

// Problem constants (fixed by reference setup_inputs)
#define B 32
#define C 256
#define SPATIAL 4096
#define NCHUNK 32
#define ROWS_PER_CHUNK 128                  // SPATIAL / NCHUNK
#define X_ELEMS (B * SPATIAL * C)           // 33554432
#define BN_EPS 1e-3f

#define NSEG 4
#define B_SEG (B / NSEG)                    // 8 batches per segment (33.5MB)

// Device state (reset each launch)
__device__ float g_psum[B][NCHUNK][C];
__device__ float g_pmax[B][NCHUNK][C];
__device__ float g_gate[B][C];
__device__ unsigned int g_done[B];

__global__ void reset_kernel()
{
    const int t = threadIdx.x;
    if (t < B) g_done[t] = 0u;
}

// ---------------------------------------------------------------------------
// poolgate: per-(batch,chunk) partial sum/max; the LAST block of each batch
// finishes the reduction (fixed order) and computes the gate inline.
// grid (NCHUNK, B_SEG), block 256.
// ---------------------------------------------------------------------------
__global__ __launch_bounds__(256) void poolgate_kernel(
    const float* __restrict__ in,
    const float* __restrict__ factor,
    const float* __restrict__ W1,
    const float* __restrict__ b1,
    const float* __restrict__ gamma,
    const float* __restrict__ beta,
    const float* __restrict__ bn_mean,
    const float* __restrict__ bn_var,
    const float* __restrict__ Wg,
    const float* __restrict__ bg,
    const float* __restrict__ gumbel,
    float* __restrict__ gate_out,       // (B, C) tail of d_out
    int b0)
{
    __shared__ float4 sh_s[256];
    __shared__ float4 sh_m[256];
    __shared__ float  pool_s[C];
    __shared__ int    sh_last;

    const int tid   = threadIdx.x;
    const int chunk = blockIdx.x;
    const int b     = b0 + blockIdx.y;

    const int c4 = (tid & 63) << 2;
    const int rg = tid >> 6;
    const float4* p = reinterpret_cast<const float4*>(
        in + ((size_t)(b * SPATIAL + chunk * ROWS_PER_CHUNK + rg)) * C + c4);

    float4 s = make_float4(0.f, 0.f, 0.f, 0.f);
    float4 m = make_float4(-INFINITY, -INFINITY, -INFINITY, -INFINITY);
#pragma unroll
    for (int i = 0; i < ROWS_PER_CHUNK / 4; ++i) {
        const float4 v = p[(size_t)i * C];
        s.x += v.x; s.y += v.y; s.z += v.z; s.w += v.w;
        m.x = fmaxf(m.x, v.x); m.y = fmaxf(m.y, v.y);
        m.z = fmaxf(m.z, v.z); m.w = fmaxf(m.w, v.w);
    }
    sh_s[tid] = s; sh_m[tid] = m;
    __syncthreads();

    if (tid < 64) {
        float4 S = sh_s[tid];
        float4 M = sh_m[tid];
#pragma unroll
        for (int g = 1; g < 4; ++g) {
            const float4 s2 = sh_s[tid + 64 * g];
            const float4 m2 = sh_m[tid + 64 * g];
            S.x += s2.x; S.y += s2.y; S.z += s2.z; S.w += s2.w;
            M.x = fmaxf(M.x, m2.x); M.y = fmaxf(M.y, m2.y);
            M.z = fmaxf(M.z, m2.z); M.w = fmaxf(M.w, m2.w);
        }
        *reinterpret_cast<float4*>(&g_psum[b][chunk][tid << 2]) = S;
        *reinterpret_cast<float4*>(&g_pmax[b][chunk][tid << 2]) = M;
        __threadfence();               // publish partials before done-count
    }
    __syncthreads();
    if (tid == 0)
        sh_last = (atomicAdd(&g_done[b], 1u) == NCHUNK - 1) ? 1 : 0;
    __syncthreads();

    if (sh_last) {
        __threadfence();               // acquire all partials
        float s1 = 0.f, m1 = -INFINITY;
#pragma unroll
        for (int k = 0; k < NCHUNK; ++k) {
            s1 += g_psum[b][k][tid];
            m1 = fmaxf(m1, g_pmax[b][k][tid]);
        }
        const float avg = s1 * (1.0f / (float)SPATIAL);
        const float a0 = factor[0], a1 = factor[1];
        const float fm = fmaxf(a0, a1);
        const float e0 = expf(a0 - fm), e1 = expf(a1 - fm);
        const float inv = 1.0f / (e0 + e1);
        pool_s[tid] = avg * (e0 * inv) + m1 * (e1 * inv);
        __syncthreads();

        float acc = 0.f;
#pragma unroll 8
        for (int k = 0; k < C; ++k)
            acc = fmaf(pool_s[k], W1[k * C + tid], acc);
        float h = acc + b1[tid];
        h = gamma[tid] * (h - bn_mean[tid]) *
                (1.0f / sqrtf(bn_var[tid] + BN_EPS)) + beta[tid];
        h = fmaxf(h, 0.f);

        const float l0 = fmaf(h, Wg[tid * 2 + 0], bg[tid * 2 + 0]);
        const float l1 = fmaf(h, Wg[tid * 2 + 1], bg[tid * 2 + 1]);
        const float z0 = l0 + gumbel[(b * C + tid) * 2 + 0];
        const float z1 = l1 + gumbel[(b * C + tid) * 2 + 1];
        const float zm = fmaxf(z0, z1);
        const float q0 = expf(z0 - zm), q1 = expf(z1 - zm);
        const float y1 = q1 / (q0 + q1);
        const float hard1 = (z1 > z0) ? 1.0f : 0.0f;   // argmax tie -> 0
        const float w = (hard1 - y1) + y1;             // stop_grad ST

        g_gate[b][tid] = w;
        gate_out[b * C + tid] = w;
    }
}

// ---------------------------------------------------------------------------
// applyGate over ONE segment. Runs on a forked stream, event-ordered after
// poolgate(seg): its input reads were just cached by that A-pass (33.5MB
// reuse distance << 126MB L2). __stcs writes don't displace the cached input.
// ---------------------------------------------------------------------------
#define SEG_F4    (X_ELEMS / NSEG / 4)       // 2097152 float4 per segment
#define C_PER_BLK 2048                       // 256 thr * 8 float4
#define C_BLOCKS  (SEG_F4 / C_PER_BLK)       // 1024 per segment

__global__ __launch_bounds__(256) void apply_gate_kernel(
    const float4* __restrict__ in4,
    float4* __restrict__ out4,
    int b0)
{
    const int tid = threadIdx.x;
    const size_t base = (size_t)(b0 * (SPATIAL * C / 4))
                      + (size_t)blockIdx.x * C_PER_BLK;

    // whole block inside one batch; channel phase shared by all 8 chunks
    const int b  = (int)(base >> 18);        // (idx*4) >> 20
    const int c4 = (tid & 63) << 2;
    const float4 g = *reinterpret_cast<const float4*>(&g_gate[b][c4]);

    float4 v[8];
#pragma unroll
    for (int k = 0; k < 8; ++k)
        v[k] = in4[base + (size_t)k * 256 + tid];
#pragma unroll
    for (int k = 0; k < 8; ++k) {
        v[k].x *= g.x; v[k].y *= g.y; v[k].z *= g.z; v[k].w *= g.w;
    }
#pragma unroll
    for (int k = 0; k < 8; ++k)
        __stcs(&out4[base + (size_t)k * 256 + tid], v[k]);
}

extern "C" void kernel_launch(void* const* d_in, const int* in_sizes, int n_in,
                              void* d_out, int out_size)
{
    const float* inputs = (const float*)d_in[0];
    const float* factor = (const float*)d_in[1];
    const float* W1     = (const float*)d_in[2];
    const float* b1     = (const float*)d_in[3];
    const float* gamma  = (const float*)d_in[4];
    const float* beta   = (const float*)d_in[5];
    const float* bnm    = (const float*)d_in[6];
    const float* bnv    = (const float*)d_in[7];
    const float* Wg     = (const float*)d_in[8];
    const float* bg     = (const float*)d_in[9];
    const float* gumbel = (const float*)d_in[10];

    float* out = (float*)d_out;
    float* gate_out = out + X_ELEMS;

    // lazily-created side stream + events (host resources only, created once)
    static cudaStream_t s2 = nullptr;
    static cudaEvent_t  evA[NSEG];
    static cudaEvent_t  evDone = nullptr;
    if (s2 == nullptr) {
        cudaStreamCreateWithFlags(&s2, cudaStreamNonBlocking);
        for (int i = 0; i < NSEG; ++i)
            cudaEventCreateWithFlags(&evA[i], cudaEventDisableTiming);
        cudaEventCreateWithFlags(&evDone, cudaEventDisableTiming);
    }

    reset_kernel<<<1, 32>>>();

    for (int s = 0; s < NSEG; ++s) {
        const int b0 = s * B_SEG;
        dim3 gridA(NCHUNK, B_SEG);
        poolgate_kernel<<<gridA, 256>>>(inputs, factor, W1, b1, gamma, beta,
                                        bnm, bnv, Wg, bg, gumbel, gate_out, b0);
        cudaEventRecord(evA[s], 0);

        cudaStreamWaitEvent(s2, evA[s], 0);
        apply_gate_kernel<<<C_BLOCKS, 256, 0, s2>>>(
            (const float4*)inputs, (float4*)out, b0);
    }
    cudaEventRecord(evDone, s2);
    cudaStreamWaitEvent(0, evDone, 0);
}

// round 17
// speedup vs baseline: 1.7906x; 1.7906x over previous
#include <cuda_runtime.h>
#include <math.h>

// Problem constants (fixed by reference setup_inputs)
#define B 32
#define C 256
#define SPATIAL 4096
#define NCHUNK 32
#define ROWS_PER_CHUNK 128                  // SPATIAL / NCHUNK
#define X_ELEMS (B * SPATIAL * C)           // 33554432
#define BN_EPS 1e-3f

// Device state (reset each launch)
__device__ float g_psum[B][NCHUNK][C];
__device__ float g_pmax[B][NCHUNK][C];
__device__ float g_gate[B][C];
__device__ unsigned int g_done[B];

__global__ void reset_kernel()
{
    const int t = threadIdx.x;
    if (t < B) g_done[t] = 0u;
}

// ---------------------------------------------------------------------------
// Kernel AB: full-grid (NCHUNK, B) pool partials; the LAST block to finish
// each batch completes the reduction (fixed order) and computes the gate
// inline (dense 256x256 + BN + ReLU + gumbel hard gate). Deterministic.
// ---------------------------------------------------------------------------
__global__ __launch_bounds__(256) void poolgate_kernel(
    const float* __restrict__ in,
    const float* __restrict__ factor,
    const float* __restrict__ W1,
    const float* __restrict__ b1,
    const float* __restrict__ gamma,
    const float* __restrict__ beta,
    const float* __restrict__ bn_mean,
    const float* __restrict__ bn_var,
    const float* __restrict__ Wg,
    const float* __restrict__ bg,
    const float* __restrict__ gumbel,
    float* __restrict__ gate_out)       // (B, C) tail of d_out
{
    __shared__ float4 sh_s[256];
    __shared__ float4 sh_m[256];
    __shared__ float  pool_s[C];
    __shared__ int    sh_last;

    const int tid   = threadIdx.x;
    const int chunk = blockIdx.x;
    const int b     = blockIdx.y;

    const int c4 = (tid & 63) << 2;
    const int rg = tid >> 6;
    const float4* p = reinterpret_cast<const float4*>(
        in + ((size_t)(b * SPATIAL + chunk * ROWS_PER_CHUNK + rg)) * C + c4);

    float4 s = make_float4(0.f, 0.f, 0.f, 0.f);
    float4 m = make_float4(-INFINITY, -INFINITY, -INFINITY, -INFINITY);
#pragma unroll
    for (int i = 0; i < ROWS_PER_CHUNK / 4; ++i) {
        const float4 v = p[(size_t)i * C];   // stride 4 rows = C float4
        s.x += v.x; s.y += v.y; s.z += v.z; s.w += v.w;
        m.x = fmaxf(m.x, v.x); m.y = fmaxf(m.y, v.y);
        m.z = fmaxf(m.z, v.z); m.w = fmaxf(m.w, v.w);
    }
    sh_s[tid] = s; sh_m[tid] = m;
    __syncthreads();

    if (tid < 64) {
        float4 S = sh_s[tid];
        float4 M = sh_m[tid];
#pragma unroll
        for (int g = 1; g < 4; ++g) {
            const float4 s2 = sh_s[tid + 64 * g];
            const float4 m2 = sh_m[tid + 64 * g];
            S.x += s2.x; S.y += s2.y; S.z += s2.z; S.w += s2.w;
            M.x = fmaxf(M.x, m2.x); M.y = fmaxf(M.y, m2.y);
            M.z = fmaxf(M.z, m2.z); M.w = fmaxf(M.w, m2.w);
        }
        *reinterpret_cast<float4*>(&g_psum[b][chunk][tid << 2]) = S;
        *reinterpret_cast<float4*>(&g_pmax[b][chunk][tid << 2]) = M;
        __threadfence();               // publish partials before done-count
    }
    __syncthreads();
    if (tid == 0)
        sh_last = (atomicAdd(&g_done[b], 1u) == NCHUNK - 1) ? 1 : 0;
    __syncthreads();

    if (sh_last) {
        __threadfence();               // acquire all partials for batch b
        float s1 = 0.f, m1 = -INFINITY;
#pragma unroll
        for (int k = 0; k < NCHUNK; ++k) {
            s1 += g_psum[b][k][tid];
            m1 = fmaxf(m1, g_pmax[b][k][tid]);
        }
        const float avg = s1 * (1.0f / (float)SPATIAL);
        const float a0 = factor[0], a1 = factor[1];
        const float fm = fmaxf(a0, a1);
        const float e0 = expf(a0 - fm), e1 = expf(a1 - fm);
        const float inv = 1.0f / (e0 + e1);
        pool_s[tid] = avg * (e0 * inv) + m1 * (e1 * inv);
        __syncthreads();

        float acc = 0.f;
#pragma unroll 8
        for (int k = 0; k < C; ++k)
            acc = fmaf(pool_s[k], W1[k * C + tid], acc);
        float h = acc + b1[tid];
        h = gamma[tid] * (h - bn_mean[tid]) *
                (1.0f / sqrtf(bn_var[tid] + BN_EPS)) + beta[tid];
        h = fmaxf(h, 0.f);

        const float l0 = fmaf(h, Wg[tid * 2 + 0], bg[tid * 2 + 0]);
        const float l1 = fmaf(h, Wg[tid * 2 + 1], bg[tid * 2 + 1]);
        const float z0 = l0 + gumbel[(b * C + tid) * 2 + 0];
        const float z1 = l1 + gumbel[(b * C + tid) * 2 + 1];
        const float zm = fmaxf(z0, z1);
        const float q0 = expf(z0 - zm), q1 = expf(z1 - zm);
        const float y1 = q1 / (q0 + q1);
        const float hard1 = (z1 > z0) ? 1.0f : 0.0f;   // argmax tie -> 0
        const float w = (hard1 - y1) + y1;             // stop_grad ST

        g_gate[b][tid] = w;
        gate_out[b * C + tid] = w;
    }
}

// ---------------------------------------------------------------------------
// Kernel C (R10 best shape): x = inputs * gate.
//  * 1024 float4 per block, 4 float4/thread, warp-coalesced (base+k*256+tid)
//  * reversed block order: reads what A cached most recently first
//  * __ldcs input reads: miss fills are evict-first -> C's own misses don't
//    evict the A-cached lines it will read later
//  * __stcs output stores: write stream doesn't evict the cached input
// ---------------------------------------------------------------------------
#define C_F4      (X_ELEMS / 4)          // 8388608 float4
#define C_PER_BLK 1024                   // float4 per block (256 thr * 4)
#define C_BLOCKS  (C_F4 / C_PER_BLK)     // 8192

__global__ __launch_bounds__(256) void apply_gate_kernel(
    const float4* __restrict__ in4,
    float4* __restrict__ out4)
{
    const int blk  = (C_BLOCKS - 1) - blockIdx.x;   // reversed
    const int tid  = threadIdx.x;
    const size_t base = (size_t)blk * C_PER_BLK;

    const size_t i0 = base + 0 * 256 + tid;
    const size_t i1 = base + 1 * 256 + tid;
    const size_t i2 = base + 2 * 256 + tid;
    const size_t i3 = base + 3 * 256 + tid;

    const int c0 = (int)((i0 << 2) & (C - 1));
    const int c1 = (int)((i1 << 2) & (C - 1));
    const int c2 = (int)((i2 << 2) & (C - 1));
    const int c3 = (int)((i3 << 2) & (C - 1));
    const int b0  = (int)(i0 >> 18);   // (i*4) >> 20
    const int b1_ = (int)(i1 >> 18);
    const int b2  = (int)(i2 >> 18);
    const int b3  = (int)(i3 >> 18);

    float4 v0 = __ldcs(&in4[i0]);
    float4 v1 = __ldcs(&in4[i1]);
    float4 v2 = __ldcs(&in4[i2]);
    float4 v3 = __ldcs(&in4[i3]);

    const float4 g0 = *reinterpret_cast<const float4*>(&g_gate[b0][c0]);
    const float4 g1 = *reinterpret_cast<const float4*>(&g_gate[b1_][c1]);
    const float4 g2 = *reinterpret_cast<const float4*>(&g_gate[b2][c2]);
    const float4 g3 = *reinterpret_cast<const float4*>(&g_gate[b3][c3]);

    v0.x *= g0.x; v0.y *= g0.y; v0.z *= g0.z; v0.w *= g0.w;
    v1.x *= g1.x; v1.y *= g1.y; v1.z *= g1.z; v1.w *= g1.w;
    v2.x *= g2.x; v2.y *= g2.y; v2.z *= g2.z; v2.w *= g2.w;
    v3.x *= g3.x; v3.y *= g3.y; v3.z *= g3.z; v3.w *= g3.w;

    __stcs(&out4[i0], v0);
    __stcs(&out4[i1], v1);
    __stcs(&out4[i2], v2);
    __stcs(&out4[i3], v3);
}

extern "C" void kernel_launch(void* const* d_in, const int* in_sizes, int n_in,
                              void* d_out, int out_size)
{
    const float* inputs = (const float*)d_in[0];
    const float* factor = (const float*)d_in[1];
    const float* W1     = (const float*)d_in[2];
    const float* b1     = (const float*)d_in[3];
    const float* gamma  = (const float*)d_in[4];
    const float* beta   = (const float*)d_in[5];
    const float* bnm    = (const float*)d_in[6];
    const float* bnv    = (const float*)d_in[7];
    const float* Wg     = (const float*)d_in[8];
    const float* bg     = (const float*)d_in[9];
    const float* gumbel = (const float*)d_in[10];

    float* out = (float*)d_out;
    float* gate_out = out + X_ELEMS;   // (B, C) broadcast gate after x

    reset_kernel<<<1, 32>>>();

    dim3 gridA(NCHUNK, B);
    poolgate_kernel<<<gridA, 256>>>(inputs, factor, W1, b1, gamma, beta,
                                    bnm, bnv, Wg, bg, gumbel, gate_out);

    apply_gate_kernel<<<C_BLOCKS, 256>>>((const float4*)inputs, (float4*)out);
}